// round 16
// baseline (speedup 1.0000x reference)
#include <cuda_runtime.h>
#include <cuda_bf16.h>
#include <math.h>
#include <stdint.h>

// Problem constants
#define NN   102400      // nodes
#define EE   1228800     // edges
#define NB   2048        // graphs
#define TT   50          // nodes per graph
#define EPG  600         // edges per graph
#define KIN  576         // IN + POS
#define HH   512         // hidden / out
#define POSD 64

#define CH   64          // channels per aggregation block
#define WSTR 576         // global stride of pre-split weight rows [n][k]

// pipeline stage layout (bytes): A 128 rows x 16 bf16, B 256 rows x 16 bf16
#define A_HI_OFF 0
#define A_LO_OFF 4096
#define B_HI_OFF 8192
#define B_LO_OFF 16384
#define STG2_B   24576           // bytes per stage
// 2 stages x 24576 = 49152 B static shared (= 48KB limit exactly)

// ---------------- scratch (static device globals) ---------------------------
__device__ uint16_t g_whi[4][(size_t)HH * WSTR];  // weights [n][k] hi
__device__ uint16_t g_wlo[4][(size_t)HH * WSTR];  // weights [n][k] lo
__device__ float g_t [(size_t)NN * HH];
__device__ float g_p1[(size_t)NN * HH];
__device__ float g_p2[(size_t)NN * HH];
__device__ float g_p3[(size_t)NN * HH];
__device__ float g_norm[EE];
__device__ float g_dinv[NN];
__device__ float g_deg [NN];
__device__ float g_stats[2 * HH];
__device__ float g_scale[3 * HH];
__device__ float g_shift[3 * HH];
// CSR (dst-sorted) edge data, built once per launch
__device__ uint16_t g_srt_src[EE];
__device__ float    g_srt_nrm[EE];
__device__ int      g_rp[NB][64];

// ---------------- helpers ---------------------------------------------------
__device__ __forceinline__ void split_bf16(float v, uint16_t& h, uint16_t& l)
{
    __nv_bfloat16 hb = __float2bfloat16(v);
    h = __bfloat16_as_ushort(hb);
    l = __bfloat16_as_ushort(__float2bfloat16(v - __bfloat162float(hb)));
}
__device__ __forceinline__ void mma_bf16(float* c, const uint32_t* a,
                                         uint32_t b0, uint32_t b1)
{
    asm volatile(
        "mma.sync.aligned.m16n8k16.row.col.f32.bf16.bf16.f32 "
        "{%0,%1,%2,%3}, {%4,%5,%6,%7}, {%8,%9}, {%0,%1,%2,%3};"
        : "+f"(c[0]), "+f"(c[1]), "+f"(c[2]), "+f"(c[3])
        : "r"(a[0]), "r"(a[1]), "r"(a[2]), "r"(a[3]), "r"(b0), "r"(b1));
}
__device__ __forceinline__ void cpa16(uint32_t s, const void* g)
{
    asm volatile("cp.async.ca.shared.global [%0], [%1], 16;" :: "r"(s), "l"(g));
}
#define CPA_COMMIT() asm volatile("cp.async.commit_group;" ::: "memory")
template<int N> __device__ __forceinline__ void cpa_wait()
{
    asm volatile("cp.async.wait_group %0;" :: "n"(N) : "memory");
}
// swizzled byte offset within one [rows x 16 bf16] array: row r, 4B-word w (0..7)
__device__ __forceinline__ int swb(int r, int w)
{
    return ((r * 2 + ((w >> 2) ^ ((r >> 2) & 1))) << 4) | ((w & 3) << 2);
}

// ---------------- degree / normalization ------------------------------------
__global__ void deg_init_k()
{
    int i = blockIdx.x * blockDim.x + threadIdx.x;
    if (i < NN) g_deg[i] = 1.0f;
}
__global__ void deg_acc_k(const int* __restrict__ dst, const float* __restrict__ w)
{
    int e = blockIdx.x * blockDim.x + threadIdx.x;
    if (e < EE) atomicAdd(&g_deg[dst[e]], w[e]);
}
__global__ void dinv_k()
{
    int i = blockIdx.x * blockDim.x + threadIdx.x;
    if (i < NN) g_dinv[i] = rsqrtf(g_deg[i]);
}
__global__ void norm_k(const int* __restrict__ src, const int* __restrict__ dst,
                       const float* __restrict__ w)
{
    int e = blockIdx.x * blockDim.x + threadIdx.x;
    if (e < EE) g_norm[e] = g_dinv[src[e]] * w[e] * g_dinv[dst[e]];
}

// ---------------- CSR build: sort edges by destination (deterministic) ------
__global__ void __launch_bounds__(64) csr_k(const int* __restrict__ src,
                                            const int* __restrict__ dst)
{
    __shared__ int cnt[TT];
    __shared__ int rp[TT + 1];
    const int b = blockIdx.x, tid = threadIdx.x;
    if (tid < TT) cnt[tid] = 0;
    __syncthreads();
    for (int e = tid; e < EPG; e += 64)
        atomicAdd(&cnt[dst[b * EPG + e] - b * TT], 1);
    __syncthreads();
    if (tid == 0) {
        int s = 0;
        for (int n = 0; n < TT; ++n) { rp[n] = s; s += cnt[n]; }
        rp[TT] = s;
    }
    __syncthreads();
    for (int i = tid; i <= TT; i += 64) g_rp[b][i] = rp[i];
    // deterministic scatter: thread per dst node scans edges in order
    if (tid < TT) {
        int p = rp[tid];
        for (int e = 0; e < EPG; ++e) {
            if (dst[b * EPG + e] - b * TT == tid) {
                g_srt_src[b * EPG + p] = (uint16_t)(src[b * EPG + e] - b * TT);
                g_srt_nrm[b * EPG + p] = g_norm[b * EPG + e];
                ++p;
            }
        }
    }
}

// ---------------- weight prep (coalesced smem transpose) ---------------------
// W[k][n] fp32 -> g_whi/g_wlo [n][k] bf16. 64x64 tile per block, 256 threads.
template<int L>
__global__ void __launch_bounds__(256) wprep_k(const float* __restrict__ W)
{
    __shared__ float tile[64][65];
    const int k0 = blockIdx.x * 64;
    const int n0 = blockIdx.y * 64;
    const int t  = threadIdx.x;
    // load 64x64 (coalesced along n)
    #pragma unroll
    for (int i = 0; i < 16; ++i) {
        int k = (t >> 6) + i * 4, n = t & 63;
        tile[k][n] = W[(size_t)(k0 + k) * HH + n0 + n];
    }
    __syncthreads();
    // write transposed (coalesced along k)
    #pragma unroll
    for (int i = 0; i < 16; ++i) {
        int n = (t >> 6) + i * 4, k = t & 63;
        uint16_t h, l;
        split_bf16(tile[k][n], h, l);
        g_whi[L][(size_t)(n0 + n) * WSTR + k0 + k] = h;
        g_wlo[L][(size_t)(n0 + n) * WSTR + k0 + k] = l;
    }
}

// ---------------- split-bf16 HMMA GEMM, CTA 128x256, warp tile 64x64 --------
// Single-sync ping-pong: at chunk c, MMA stage c&1 while loaders fill stage
// (c+1)&1. A fp32 via register prefetch with fused concat / BN+ReLU /
// 3-way residual combine; split to bf16 at STS. B via cp.async.
// ASRC: 0 = concat(x||posemb[pos]) ; 1 = g_p1 ; 2 = g_p2 ;
//       4 = relu(bn(p1))+relu(bn(p2))+relu(bn(p3)) (fused combine)
// ACTL: BN layer index or -1. MODE 0: C->g_t ; 1: tanh+bias->out.
template<int MODE, int ASRC, int ACTL, int KDIM, int WL>
__global__ void __launch_bounds__(256, 1) gemm_hmma(
    const float* __restrict__ xin, const int* __restrict__ pos,
    const float* __restrict__ pemb,
    float* __restrict__ outC, const float* __restrict__ bias)
{
    __shared__ __align__(16) uint8_t smem2[2 * STG2_B];

    const int tid  = threadIdx.x;
    const int wid  = tid >> 5;
    const int lane = tid & 31;
    const int g    = lane >> 2;
    const int tig  = lane & 3;
    const int wm   = wid >> 2;         // warp m-tile 0..1 (64 rows)
    const int wn   = wid & 3;          // warp n-tile 0..3 (64 cols)

    const int n0 = blockIdx.x * 256;
    const size_t rowBase = (size_t)blockIdx.y * 128;
    const uint16_t* Whi = g_whi[WL];
    const uint16_t* Wlo = g_wlo[WL];

    const uint32_t smemBase = (uint32_t)__cvta_generic_to_shared(smem2);
    // loader coordinates: thread -> (row cr, 16B-unit cu)
    const int cr = tid >> 1;
    const int cu = tid & 1;
    uint8_t* const pA = smem2 + ((cr * 2 + (cu ^ ((cr >> 2) & 1))) << 4);
    const int br1 = cr + 128;
    const uint32_t dB0 = smemBase + (uint32_t)((cr * 2 + (cu ^ ((cr >> 2) & 1))) << 4);
    const uint32_t dB1 = smemBase + (uint32_t)((br1 * 2 + (cu ^ ((br1 >> 2) & 1))) << 4);
    const size_t bSrc0 = (size_t)(n0 + cr) * WSTR + cu * 8;
    const size_t bSrc1 = (size_t)(n0 + br1) * WSTR + cu * 8;

    // A source row pointers (fp32)
    const float* Arow;
    if (ASRC == 0)      Arow = xin + (rowBase + cr) * 512;
    else if (ASRC == 1) Arow = g_p1 + (rowBase + cr) * HH;
    else if (ASRC == 2) Arow = g_p2 + (rowBase + cr) * HH;
    else                Arow = g_p1 + (rowBase + cr) * HH;
    const float* Arow2 = (ASRC == 4) ? (g_p2 + (rowBase + cr) * HH) : nullptr;
    const float* Arow3 = (ASRC == 4) ? (g_p3 + (rowBase + cr) * HH) : nullptr;
    const float* Prow = (ASRC == 0) ? (pemb + (size_t)pos[rowBase + cr] * POSD) : nullptr;

    float acc[4][8][4];
    #pragma unroll
    for (int fm = 0; fm < 4; ++fm)
        #pragma unroll
        for (int fn = 0; fn < 8; ++fn)
            #pragma unroll
            for (int q = 0; q < 4; ++q) acc[fm][fn][q] = 0.f;

    constexpr int CHUNKS = KDIM / 16;

    auto issueB = [&](int c) {
        if (c < CHUNKS) {
            const int k0 = c * 16;
            const uint32_t sb = (uint32_t)(c & 1) * STG2_B;
            cpa16(dB0 + sb + B_HI_OFF, Whi + bSrc0 + k0);
            cpa16(dB0 + sb + B_LO_OFF, Wlo + bSrc0 + k0);
            cpa16(dB1 + sb + B_HI_OFF, Whi + bSrc1 + k0);
            cpa16(dB1 + sb + B_LO_OFF, Wlo + bSrc1 + k0);
        }
        CPA_COMMIT();
    };

    // prefetch & pre-process A for chunk c (off the critical path)
    auto ldA = [&](int c, float4* r, float4* rs, float4* rh) {
        if (c >= CHUNKS) return;
        const int k = c * 16 + cu * 8;
        if (ASRC == 0 && k >= 512) {
            r[0] = *(const float4*)(Prow + (k - 512));
            r[1] = *(const float4*)(Prow + (k - 512) + 4);
        } else if (ASRC == 4) {
            // fused combine: relu(bn1(p1)) + relu(bn2(p2)) + relu(bn3(p3))
            #pragma unroll
            for (int u = 0; u < 2; ++u) {
                float4 v1 = *(const float4*)(Arow  + k + u * 4);
                float4 v2 = *(const float4*)(Arow2 + k + u * 4);
                float4 v3 = *(const float4*)(Arow3 + k + u * 4);
                float4 s1 = *(const float4*)(g_scale + k + u * 4);
                float4 h1 = *(const float4*)(g_shift + k + u * 4);
                float4 s2 = *(const float4*)(g_scale + HH + k + u * 4);
                float4 h2 = *(const float4*)(g_shift + HH + k + u * 4);
                float4 s3 = *(const float4*)(g_scale + 2 * HH + k + u * 4);
                float4 h3 = *(const float4*)(g_shift + 2 * HH + k + u * 4);
                float4 o;
                o.x = fmaxf(fmaf(v1.x, s1.x, h1.x), 0.f)
                    + fmaxf(fmaf(v2.x, s2.x, h2.x), 0.f)
                    + fmaxf(fmaf(v3.x, s3.x, h3.x), 0.f);
                o.y = fmaxf(fmaf(v1.y, s1.y, h1.y), 0.f)
                    + fmaxf(fmaf(v2.y, s2.y, h2.y), 0.f)
                    + fmaxf(fmaf(v3.y, s3.y, h3.y), 0.f);
                o.z = fmaxf(fmaf(v1.z, s1.z, h1.z), 0.f)
                    + fmaxf(fmaf(v2.z, s2.z, h2.z), 0.f)
                    + fmaxf(fmaf(v3.z, s3.z, h3.z), 0.f);
                o.w = fmaxf(fmaf(v1.w, s1.w, h1.w), 0.f)
                    + fmaxf(fmaf(v2.w, s2.w, h2.w), 0.f)
                    + fmaxf(fmaf(v3.w, s3.w, h3.w), 0.f);
                r[u] = o;
            }
        } else {
            r[0] = *(const float4*)(Arow + k);
            r[1] = *(const float4*)(Arow + k + 4);
        }
        if (ACTL >= 0) {
            rs[0] = *(const float4*)(g_scale + ACTL * HH + k);
            rs[1] = *(const float4*)(g_scale + ACTL * HH + k + 4);
            rh[0] = *(const float4*)(g_shift + ACTL * HH + k);
            rh[1] = *(const float4*)(g_shift + ACTL * HH + k + 4);
        }
    };

    auto stsA = [&](int c, const float4* r, const float4* rs, const float4* rh) {
        if (c >= CHUNKS) return;
        float4 v0 = r[0], v1 = r[1];
        if (ACTL >= 0) {
            v0.x = fmaxf(fmaf(v0.x, rs[0].x, rh[0].x), 0.f);
            v0.y = fmaxf(fmaf(v0.y, rs[0].y, rh[0].y), 0.f);
            v0.z = fmaxf(fmaf(v0.z, rs[0].z, rh[0].z), 0.f);
            v0.w = fmaxf(fmaf(v0.w, rs[0].w, rh[0].w), 0.f);
            v1.x = fmaxf(fmaf(v1.x, rs[1].x, rh[1].x), 0.f);
            v1.y = fmaxf(fmaf(v1.y, rs[1].y, rh[1].y), 0.f);
            v1.z = fmaxf(fmaf(v1.z, rs[1].z, rh[1].z), 0.f);
            v1.w = fmaxf(fmaf(v1.w, rs[1].w, rh[1].w), 0.f);
        }
        uint16_t h[8], l[8];
        split_bf16(v0.x, h[0], l[0]); split_bf16(v0.y, h[1], l[1]);
        split_bf16(v0.z, h[2], l[2]); split_bf16(v0.w, h[3], l[3]);
        split_bf16(v1.x, h[4], l[4]); split_bf16(v1.y, h[5], l[5]);
        split_bf16(v1.z, h[6], l[6]); split_bf16(v1.w, h[7], l[7]);
        uint4 uh, ul;
        uh.x = ((uint32_t)h[1] << 16) | h[0]; uh.y = ((uint32_t)h[3] << 16) | h[2];
        uh.z = ((uint32_t)h[5] << 16) | h[4]; uh.w = ((uint32_t)h[7] << 16) | h[6];
        ul.x = ((uint32_t)l[1] << 16) | l[0]; ul.y = ((uint32_t)l[3] << 16) | l[2];
        ul.z = ((uint32_t)l[5] << 16) | l[4]; ul.w = ((uint32_t)l[7] << 16) | l[6];
        const uint32_t sb = (uint32_t)(c & 1) * STG2_B;
        *(uint4*)(pA + sb + A_HI_OFF) = uh;
        *(uint4*)(pA + sb + A_LO_OFF) = ul;
    };

    // fragment smem byte offsets (within an array), fixed per thread
    int offA[4][4], offB[8][2];
    #pragma unroll
    for (int fm = 0; fm < 4; ++fm) {
        int r0 = wm * 64 + fm * 16 + g;
        offA[fm][0] = swb(r0,     tig);
        offA[fm][1] = swb(r0 + 8, tig);
        offA[fm][2] = swb(r0,     tig + 4);
        offA[fm][3] = swb(r0 + 8, tig + 4);
    }
    #pragma unroll
    for (int fn = 0; fn < 8; ++fn) {
        int bn = wn * 64 + fn * 8 + g;
        offB[fn][0] = swb(bn, tig);
        offB[fn][1] = swb(bn, tig + 4);
    }

    // prologue: fill stage 0 completely, prefetch chunk-1 A
    float4 rA[2], rS[2], rH[2];
    issueB(0);
    ldA(0, rA, rS, rH);
    stsA(0, rA, rS, rH);
    ldA(1, rA, rS, rH);
    cpa_wait<0>();
    __syncthreads();

    for (int c = 0; c < CHUNKS; ++c) {
        // loaders fill stage (c+1)&1 while MMA consumes stage c&1
        issueB(c + 1);
        stsA(c + 1, rA, rS, rH);
        ldA(c + 2, rA, rS, rH);

        const uint8_t* sb   = smem2 + (c & 1) * STG2_B;
        const uint8_t* sAhi = sb + A_HI_OFF;
        const uint8_t* sAlo = sb + A_LO_OFF;
        const uint8_t* sBhi = sb + B_HI_OFF;
        const uint8_t* sBlo = sb + B_LO_OFF;

        uint32_t af[2][4][4];
        #pragma unroll
        for (int fm = 0; fm < 4; ++fm)
            #pragma unroll
            for (int q = 0; q < 4; ++q) {
                af[0][fm][q] = *(const uint32_t*)(sAhi + offA[fm][q]);
                af[1][fm][q] = *(const uint32_t*)(sAlo + offA[fm][q]);
            }
        #pragma unroll
        for (int fn = 0; fn < 8; ++fn) {
            uint32_t bh0 = *(const uint32_t*)(sBhi + offB[fn][0]);
            uint32_t bh1 = *(const uint32_t*)(sBhi + offB[fn][1]);
            uint32_t bl0 = *(const uint32_t*)(sBlo + offB[fn][0]);
            uint32_t bl1 = *(const uint32_t*)(sBlo + offB[fn][1]);
            #pragma unroll
            for (int fm = 0; fm < 4; ++fm) {
                mma_bf16(acc[fm][fn], af[0][fm], bh0, bh1);   // hi*hi
                mma_bf16(acc[fm][fn], af[0][fm], bl0, bl1);   // hi*lo
                mma_bf16(acc[fm][fn], af[1][fm], bh0, bh1);   // lo*hi
            }
        }

        // stage (c+1) complete (cp.async + STS) before anyone reads it
        cpa_wait<0>();
        __syncthreads();
    }

    // ---- epilogue ----------------------------------------------------------
    float* Cout = (MODE == 0) ? g_t : outC;
    #pragma unroll
    for (int fm = 0; fm < 4; ++fm) {
        size_t r0 = rowBase + wm * 64 + fm * 16 + g;
        size_t r1 = r0 + 8;
        #pragma unroll
        for (int fn = 0; fn < 8; ++fn) {
            int col = n0 + wn * 64 + fn * 8 + 2 * tig;
            float2 v0, v1;
            if (MODE == 0) {
                v0.x = acc[fm][fn][0]; v0.y = acc[fm][fn][1];
                v1.x = acc[fm][fn][2]; v1.y = acc[fm][fn][3];
            } else {
                float bx = bias[col], by = bias[col + 1];
                v0.x = tanhf(acc[fm][fn][0] + bx);
                v0.y = tanhf(acc[fm][fn][1] + by);
                v1.x = tanhf(acc[fm][fn][2] + bx);
                v1.y = tanhf(acc[fm][fn][3] + by);
            }
            *(float2*)(Cout + r0 * HH + col) = v0;
            *(float2*)(Cout + r1 * HH + col) = v1;
        }
    }
}

// ---------------- per-graph aggregation (CSR, register accumulation) --------
template<int L>
__global__ void __launch_bounds__(64) agg_k(const float* __restrict__ bias)
{
    __shared__ float    sIn [TT * CH];
    __shared__ float    sNrm[EPG];
    __shared__ uint16_t sSrc[EPG];
    __shared__ int      sRp [TT + 1];
    __shared__ float    sSelf[TT];

    float* pout = (L == 0) ? g_p1 : (L == 1) ? g_p2 : g_p3;

    const int b   = blockIdx.x;
    const int c0  = blockIdx.y * CH;
    const int c   = threadIdx.x;

    const float* base = g_t + (size_t)b * TT * HH + c0;
    for (int i = c; i < TT * CH; i += 64) {
        int node = i / CH, ch = i & (CH - 1);
        sIn[i] = base[(size_t)node * HH + ch];
    }
    for (int e = c; e < EPG; e += 64) {
        sNrm[e] = g_srt_nrm[b * EPG + e];
        sSrc[e] = g_srt_src[b * EPG + e];
    }
    for (int i = c; i <= TT; i += 64) sRp[i] = g_rp[b][i];
    for (int i = c; i < TT; i += 64) {
        float d = g_dinv[b * TT + i];
        sSelf[i] = d * d;
    }
    __syncthreads();

    const float bc = bias[c0 + c];
    float sum = 0.f, sq = 0.f;
    for (int node = 0; node < TT; ++node) {
        float acc = 0.f;
        const int e1 = sRp[node + 1];
        for (int e = sRp[node]; e < e1; ++e)
            acc = fmaf(sIn[sSrc[e] * CH + c], sNrm[e], acc);
        float v = acc + sIn[node * CH + c] * sSelf[node] + bc;
        pout[(size_t)(b * TT + node) * HH + c0 + c] = v;
        sum += v;
        sq  += v * v;
    }
    atomicAdd(&g_stats[c0 + c], sum);
    atomicAdd(&g_stats[HH + c0 + c], sq);
}

// ---------------- BN finalize ------------------------------------------------
template<int L>
__global__ void bnfinal_k(const float* __restrict__ g, const float* __restrict__ be)
{
    int c = threadIdx.x;
    float s = g_stats[c], sq = g_stats[HH + c];
    const float inv = 1.0f / (float)NN;
    float mean = s * inv;
    float var  = sq * inv - mean * mean;
    float rstd = rsqrtf(var + 1e-5f);
    float scl  = g[c] * rstd;
    g_scale[L * HH + c] = scl;
    g_shift[L * HH + c] = fmaf(-mean, scl, be[c]);
    g_stats[c] = 0.f;
    g_stats[HH + c] = 0.f;
}

// ---------------- host driver: kernel launches ONLY --------------------------
extern "C" void kernel_launch(void* const* d_in, const int* in_sizes, int n_in,
                              void* d_out, int out_size)
{
    (void)in_sizes; (void)n_in; (void)out_size;

    const float* x      = (const float*)d_in[0];
    const int*   eidx   = (const int*)  d_in[1];
    const int*   esrc   = eidx;
    const int*   edst   = eidx + EE;
    const float* ew     = (const float*)d_in[2];
    const int*   pos    = (const int*)  d_in[3];
    const float* posemb = (const float*)d_in[4];
    const float* W1 = (const float*)d_in[5];
    const float* b1 = (const float*)d_in[6];
    const float* g1 = (const float*)d_in[7];
    const float* be1= (const float*)d_in[8];
    const float* W2 = (const float*)d_in[9];
    const float* b2 = (const float*)d_in[10];
    const float* g2 = (const float*)d_in[11];
    const float* be2= (const float*)d_in[12];
    const float* W3 = (const float*)d_in[13];
    const float* b3 = (const float*)d_in[14];
    const float* g3 = (const float*)d_in[15];
    const float* be3= (const float*)d_in[16];
    const float* Wl = (const float*)d_in[17];
    const float* bl = (const float*)d_in[18];
    float* out = (float*)d_out;

    dim3 aGrid(NB, HH / CH);          // (2048, 8)
    dim3 gGrid(HH / 256, NN / 128);   // (2, 800)
    dim3 wGrid1(KIN / 64, HH / 64);   // (9, 8)
    dim3 wGridH(HH / 64, HH / 64);    // (8, 8)

    // ordered so gemm1 is launch index 3 (profiled slot)
    wprep_k<0><<<wGrid1, 256>>>(W1);                      // 0
    deg_init_k<<<(NN + 255) / 256, 256>>>();              // 1
    deg_acc_k<<<(EE + 255) / 256, 256>>>(edst, ew);       // 2
    gemm_hmma<0, 0, -1, KIN, 0><<<gGrid, 256>>>(x, pos, posemb, nullptr, nullptr); // 3
    dinv_k<<<(NN + 255) / 256, 256>>>();                  // 4
    norm_k<<<(EE + 255) / 256, 256>>>(esrc, edst, ew);    // 5
    csr_k<<<NB, 64>>>(esrc, edst);                        // 6
    wprep_k<1><<<wGridH, 256>>>(W2);                      // 7

    // layer 1 aggregation + BN
    agg_k<0><<<aGrid, 64>>>(b1);
    bnfinal_k<0><<<1, HH>>>(g1, be1);

    // layer 2 (A = p1 with fused BN0+ReLU+split)
    gemm_hmma<0, 1, 0, HH, 1><<<gGrid, 256>>>(nullptr, nullptr, nullptr, nullptr, nullptr);
    wprep_k<2><<<wGridH, 256>>>(W3);
    agg_k<1><<<aGrid, 64>>>(b2);
    bnfinal_k<1><<<1, HH>>>(g2, be2);

    // layer 3 (A = p2 with fused BN1+ReLU+split)
    gemm_hmma<0, 2, 1, HH, 2><<<gGrid, 256>>>(nullptr, nullptr, nullptr, nullptr, nullptr);
    wprep_k<3><<<wGridH, 256>>>(Wl);
    agg_k<2><<<aGrid, 64>>>(b3);
    bnfinal_k<2><<<1, HH>>>(g3, be3);

    // final head with fused 3-way residual combine in the A-loader
    gemm_hmma<1, 4, -1, HH, 3><<<gGrid, 256>>>(nullptr, nullptr, nullptr, out, bl);
}

// round 17
// speedup vs baseline: 1.0334x; 1.0334x over previous
#include <cuda_runtime.h>
#include <cuda_bf16.h>
#include <math.h>
#include <stdint.h>

// Problem constants
#define NN   102400      // nodes
#define EE   1228800     // edges
#define NB   2048        // graphs
#define TT   50          // nodes per graph
#define EPG  600         // edges per graph
#define KIN  576         // IN + POS
#define HH   512         // hidden / out
#define POSD 64

#define CH   64          // channels per aggregation block
#define WSTR 576         // global stride of pre-split weight rows [n][k]

// pipeline stage layout (bytes): A 128 rows x 16 bf16, B 256 rows x 16 bf16
#define A_HI_OFF 0
#define A_LO_OFF 4096
#define B_HI_OFF 8192
#define B_LO_OFF 16384
#define STG2_B   24576           // bytes per stage
// 2 stages x 24576 = 49152 B static shared (= 48KB limit exactly)

// ---------------- scratch (static device globals) ---------------------------
__device__ uint16_t g_whi[4][(size_t)HH * WSTR];  // weights [n][k] hi
__device__ uint16_t g_wlo[4][(size_t)HH * WSTR];  // weights [n][k] lo
__device__ float g_t [(size_t)NN * HH];
__device__ float g_p1[(size_t)NN * HH];
__device__ float g_p2[(size_t)NN * HH];
__device__ float g_p3[(size_t)NN * HH];
__device__ float g_norm[EE];
__device__ float g_dinv[NN];
__device__ float g_deg [NN];
__device__ float g_stats[2 * HH];
__device__ float g_scale[3 * HH];
__device__ float g_shift[3 * HH];
// CSR (dst-sorted) edge data, built once per launch
__device__ uint16_t g_srt_src[EE];
__device__ float    g_srt_nrm[EE];
__device__ int      g_rp[NB][64];

// ---------------- helpers ---------------------------------------------------
__device__ __forceinline__ void split_bf16(float v, uint16_t& h, uint16_t& l)
{
    __nv_bfloat16 hb = __float2bfloat16(v);
    h = __bfloat16_as_ushort(hb);
    l = __bfloat16_as_ushort(__float2bfloat16(v - __bfloat162float(hb)));
}
__device__ __forceinline__ void mma_bf16(float* c, const uint32_t* a,
                                         uint32_t b0, uint32_t b1)
{
    asm volatile(
        "mma.sync.aligned.m16n8k16.row.col.f32.bf16.bf16.f32 "
        "{%0,%1,%2,%3}, {%4,%5,%6,%7}, {%8,%9}, {%0,%1,%2,%3};"
        : "+f"(c[0]), "+f"(c[1]), "+f"(c[2]), "+f"(c[3])
        : "r"(a[0]), "r"(a[1]), "r"(a[2]), "r"(a[3]), "r"(b0), "r"(b1));
}
__device__ __forceinline__ void cpa16(uint32_t s, const void* g)
{
    asm volatile("cp.async.ca.shared.global [%0], [%1], 16;" :: "r"(s), "l"(g));
}
#define CPA_COMMIT() asm volatile("cp.async.commit_group;" ::: "memory")
template<int N> __device__ __forceinline__ void cpa_wait()
{
    asm volatile("cp.async.wait_group %0;" :: "n"(N) : "memory");
}
// swizzled byte offset within one [rows x 16 bf16] array: row r, 4B-word w (0..7)
__device__ __forceinline__ int swb(int r, int w)
{
    return ((r * 2 + ((w >> 2) ^ ((r >> 2) & 1))) << 4) | ((w & 3) << 2);
}

// ---------------- degree / normalization ------------------------------------
__global__ void deg_init_k()
{
    int i = blockIdx.x * blockDim.x + threadIdx.x;
    if (i < NN) g_deg[i] = 1.0f;
}
__global__ void deg_acc_k(const int* __restrict__ dst, const float* __restrict__ w)
{
    int e = blockIdx.x * blockDim.x + threadIdx.x;
    if (e < EE) atomicAdd(&g_deg[dst[e]], w[e]);
}
__global__ void dinv_k()
{
    int i = blockIdx.x * blockDim.x + threadIdx.x;
    if (i < NN) g_dinv[i] = rsqrtf(g_deg[i]);
}
__global__ void norm_k(const int* __restrict__ src, const int* __restrict__ dst,
                       const float* __restrict__ w)
{
    int e = blockIdx.x * blockDim.x + threadIdx.x;
    if (e < EE) g_norm[e] = g_dinv[src[e]] * w[e] * g_dinv[dst[e]];
}

// ---------------- CSR build: sort edges by destination (deterministic) ------
__global__ void __launch_bounds__(64) csr_k(const int* __restrict__ src,
                                            const int* __restrict__ dst)
{
    __shared__ int cnt[TT];
    __shared__ int rp[TT + 1];
    const int b = blockIdx.x, tid = threadIdx.x;
    if (tid < TT) cnt[tid] = 0;
    __syncthreads();
    for (int e = tid; e < EPG; e += 64)
        atomicAdd(&cnt[dst[b * EPG + e] - b * TT], 1);
    __syncthreads();
    if (tid == 0) {
        int s = 0;
        for (int n = 0; n < TT; ++n) { rp[n] = s; s += cnt[n]; }
        rp[TT] = s;
    }
    __syncthreads();
    for (int i = tid; i <= TT; i += 64) g_rp[b][i] = rp[i];
    // deterministic scatter: thread per dst node scans edges in order
    if (tid < TT) {
        int p = rp[tid];
        for (int e = 0; e < EPG; ++e) {
            if (dst[b * EPG + e] - b * TT == tid) {
                g_srt_src[b * EPG + p] = (uint16_t)(src[b * EPG + e] - b * TT);
                g_srt_nrm[b * EPG + p] = g_norm[b * EPG + e];
                ++p;
            }
        }
    }
}

// ---------------- weight prep (coalesced smem transpose) ---------------------
// W[k][n] fp32 -> g_whi/g_wlo [n][k] bf16. 64x64 tile per block, 256 threads.
template<int L>
__global__ void __launch_bounds__(256) wprep_k(const float* __restrict__ W)
{
    __shared__ float tile[64][65];
    const int k0 = blockIdx.x * 64;
    const int n0 = blockIdx.y * 64;
    const int t  = threadIdx.x;
    // load 64x64 (coalesced along n)
    #pragma unroll
    for (int i = 0; i < 16; ++i) {
        int k = (t >> 6) + i * 4, n = t & 63;
        tile[k][n] = W[(size_t)(k0 + k) * HH + n0 + n];
    }
    __syncthreads();
    // write transposed (coalesced along k)
    #pragma unroll
    for (int i = 0; i < 16; ++i) {
        int n = (t >> 6) + i * 4, k = t & 63;
        uint16_t h, l;
        split_bf16(tile[k][n], h, l);
        g_whi[L][(size_t)(n0 + n) * WSTR + k0 + k] = h;
        g_wlo[L][(size_t)(n0 + n) * WSTR + k0 + k] = l;
    }
}

// ---------------- residual combine -> fp32 g_t ------------------------------
__global__ void combine_k()
{
    size_t idx = ((size_t)blockIdx.x * blockDim.x + threadIdx.x) * 4;
    int j = (int)(idx & (HH - 1));
    float4 a = *(const float4*)(g_p1 + idx);
    float4 b = *(const float4*)(g_p2 + idx);
    float4 c = *(const float4*)(g_p3 + idx);
    float4 s, h, r;
    s = *(const float4*)(g_scale + j);       h = *(const float4*)(g_shift + j);
    r.x = fmaxf(fmaf(a.x, s.x, h.x), 0.f);
    r.y = fmaxf(fmaf(a.y, s.y, h.y), 0.f);
    r.z = fmaxf(fmaf(a.z, s.z, h.z), 0.f);
    r.w = fmaxf(fmaf(a.w, s.w, h.w), 0.f);
    s = *(const float4*)(g_scale + HH + j);  h = *(const float4*)(g_shift + HH + j);
    r.x += fmaxf(fmaf(b.x, s.x, h.x), 0.f);
    r.y += fmaxf(fmaf(b.y, s.y, h.y), 0.f);
    r.z += fmaxf(fmaf(b.z, s.z, h.z), 0.f);
    r.w += fmaxf(fmaf(b.w, s.w, h.w), 0.f);
    s = *(const float4*)(g_scale + 2*HH + j); h = *(const float4*)(g_shift + 2*HH + j);
    r.x += fmaxf(fmaf(c.x, s.x, h.x), 0.f);
    r.y += fmaxf(fmaf(c.y, s.y, h.y), 0.f);
    r.z += fmaxf(fmaf(c.z, s.z, h.z), 0.f);
    r.w += fmaxf(fmaf(c.w, s.w, h.w), 0.f);
    *(float4*)(g_t + idx) = r;
}

// ---------------- split-bf16 HMMA GEMM, CTA 128x256, warp tile 64x64 --------
// Single-sync ping-pong: at chunk c, MMA stage c&1 while loaders fill stage
// (c+1)&1; ONE __syncthreads + cpa_wait per chunk -> loader overlaps MMA.
// ASRC: 0 = concat(x||posemb[pos]) ; 1 = g_p1 ; 2 = g_p2 ; 3 = g_t
// ACTL: BN layer index or -1. MODE 0: C->g_t ; 1: tanh+bias->out.
template<int MODE, int ASRC, int ACTL, int KDIM, int WL>
__global__ void __launch_bounds__(256, 1) gemm_hmma(
    const float* __restrict__ xin, const int* __restrict__ pos,
    const float* __restrict__ pemb,
    float* __restrict__ outC, const float* __restrict__ bias)
{
    __shared__ __align__(16) uint8_t smem2[2 * STG2_B];

    const int tid  = threadIdx.x;
    const int wid  = tid >> 5;
    const int lane = tid & 31;
    const int g    = lane >> 2;
    const int tig  = lane & 3;
    const int wm   = wid >> 2;         // warp m-tile 0..1 (64 rows)
    const int wn   = wid & 3;          // warp n-tile 0..3 (64 cols)

    const int n0 = blockIdx.x * 256;
    const size_t rowBase = (size_t)blockIdx.y * 128;
    const uint16_t* Whi = g_whi[WL];
    const uint16_t* Wlo = g_wlo[WL];

    const uint32_t smemBase = (uint32_t)__cvta_generic_to_shared(smem2);
    // loader coordinates: thread -> (row cr, 16B-unit cu)
    const int cr = tid >> 1;
    const int cu = tid & 1;
    uint8_t* const pA = smem2 + ((cr * 2 + (cu ^ ((cr >> 2) & 1))) << 4);
    const int br1 = cr + 128;
    const uint32_t dB0 = smemBase + (uint32_t)((cr * 2 + (cu ^ ((cr >> 2) & 1))) << 4);
    const uint32_t dB1 = smemBase + (uint32_t)((br1 * 2 + (cu ^ ((br1 >> 2) & 1))) << 4);
    const size_t bSrc0 = (size_t)(n0 + cr) * WSTR + cu * 8;
    const size_t bSrc1 = (size_t)(n0 + br1) * WSTR + cu * 8;

    // A source row pointer (fp32)
    const float* Arow;
    if (ASRC == 0)      Arow = xin + (rowBase + cr) * 512;
    else if (ASRC == 1) Arow = g_p1 + (rowBase + cr) * HH;
    else if (ASRC == 2) Arow = g_p2 + (rowBase + cr) * HH;
    else                Arow = g_t + (rowBase + cr) * HH;
    const float* Prow = (ASRC == 0) ? (pemb + (size_t)pos[rowBase + cr] * POSD) : nullptr;

    float acc[4][8][4];
    #pragma unroll
    for (int fm = 0; fm < 4; ++fm)
        #pragma unroll
        for (int fn = 0; fn < 8; ++fn)
            #pragma unroll
            for (int q = 0; q < 4; ++q) acc[fm][fn][q] = 0.f;

    constexpr int CHUNKS = KDIM / 16;

    auto issueB = [&](int c) {
        if (c < CHUNKS) {
            const int k0 = c * 16;
            const uint32_t sb = (uint32_t)(c & 1) * STG2_B;
            cpa16(dB0 + sb + B_HI_OFF, Whi + bSrc0 + k0);
            cpa16(dB0 + sb + B_LO_OFF, Wlo + bSrc0 + k0);
            cpa16(dB1 + sb + B_HI_OFF, Whi + bSrc1 + k0);
            cpa16(dB1 + sb + B_LO_OFF, Wlo + bSrc1 + k0);
        }
        CPA_COMMIT();
    };

    // prefetch A (and BN scale/shift) for chunk c into registers
    auto ldA = [&](int c, float4* r, float4* rs, float4* rh) {
        if (c >= CHUNKS) return;
        const int k = c * 16 + cu * 8;
        if (ASRC == 0 && k >= 512) {
            r[0] = *(const float4*)(Prow + (k - 512));
            r[1] = *(const float4*)(Prow + (k - 512) + 4);
        } else {
            r[0] = *(const float4*)(Arow + k);
            r[1] = *(const float4*)(Arow + k + 4);
        }
        if (ACTL >= 0) {
            rs[0] = *(const float4*)(g_scale + ACTL * HH + k);
            rs[1] = *(const float4*)(g_scale + ACTL * HH + k + 4);
            rh[0] = *(const float4*)(g_shift + ACTL * HH + k);
            rh[1] = *(const float4*)(g_shift + ACTL * HH + k + 4);
        }
    };

    auto stsA = [&](int c, const float4* r, const float4* rs, const float4* rh) {
        if (c >= CHUNKS) return;
        float4 v0 = r[0], v1 = r[1];
        if (ACTL >= 0) {
            v0.x = fmaxf(fmaf(v0.x, rs[0].x, rh[0].x), 0.f);
            v0.y = fmaxf(fmaf(v0.y, rs[0].y, rh[0].y), 0.f);
            v0.z = fmaxf(fmaf(v0.z, rs[0].z, rh[0].z), 0.f);
            v0.w = fmaxf(fmaf(v0.w, rs[0].w, rh[0].w), 0.f);
            v1.x = fmaxf(fmaf(v1.x, rs[1].x, rh[1].x), 0.f);
            v1.y = fmaxf(fmaf(v1.y, rs[1].y, rh[1].y), 0.f);
            v1.z = fmaxf(fmaf(v1.z, rs[1].z, rh[1].z), 0.f);
            v1.w = fmaxf(fmaf(v1.w, rs[1].w, rh[1].w), 0.f);
        }
        uint16_t h[8], l[8];
        split_bf16(v0.x, h[0], l[0]); split_bf16(v0.y, h[1], l[1]);
        split_bf16(v0.z, h[2], l[2]); split_bf16(v0.w, h[3], l[3]);
        split_bf16(v1.x, h[4], l[4]); split_bf16(v1.y, h[5], l[5]);
        split_bf16(v1.z, h[6], l[6]); split_bf16(v1.w, h[7], l[7]);
        uint4 uh, ul;
        uh.x = ((uint32_t)h[1] << 16) | h[0]; uh.y = ((uint32_t)h[3] << 16) | h[2];
        uh.z = ((uint32_t)h[5] << 16) | h[4]; uh.w = ((uint32_t)h[7] << 16) | h[6];
        ul.x = ((uint32_t)l[1] << 16) | l[0]; ul.y = ((uint32_t)l[3] << 16) | l[2];
        ul.z = ((uint32_t)l[5] << 16) | l[4]; ul.w = ((uint32_t)l[7] << 16) | l[6];
        const uint32_t sb = (uint32_t)(c & 1) * STG2_B;
        *(uint4*)(pA + sb + A_HI_OFF) = uh;
        *(uint4*)(pA + sb + A_LO_OFF) = ul;
    };

    // fragment smem byte offsets (within an array), fixed per thread
    int offA[4][4], offB[8][2];
    #pragma unroll
    for (int fm = 0; fm < 4; ++fm) {
        int r0 = wm * 64 + fm * 16 + g;
        offA[fm][0] = swb(r0,     tig);
        offA[fm][1] = swb(r0 + 8, tig);
        offA[fm][2] = swb(r0,     tig + 4);
        offA[fm][3] = swb(r0 + 8, tig + 4);
    }
    #pragma unroll
    for (int fn = 0; fn < 8; ++fn) {
        int bn = wn * 64 + fn * 8 + g;
        offB[fn][0] = swb(bn, tig);
        offB[fn][1] = swb(bn, tig + 4);
    }

    // prologue: fill stage 0 completely, prefetch chunk-1 A
    float4 rA[2], rS[2], rH[2];
    issueB(0);
    ldA(0, rA, rS, rH);
    stsA(0, rA, rS, rH);
    ldA(1, rA, rS, rH);
    cpa_wait<0>();
    __syncthreads();

    for (int c = 0; c < CHUNKS; ++c) {
        // loaders fill stage (c+1)&1 while MMA consumes stage c&1
        issueB(c + 1);
        stsA(c + 1, rA, rS, rH);
        ldA(c + 2, rA, rS, rH);

        const uint8_t* sb   = smem2 + (c & 1) * STG2_B;
        const uint8_t* sAhi = sb + A_HI_OFF;
        const uint8_t* sAlo = sb + A_LO_OFF;
        const uint8_t* sBhi = sb + B_HI_OFF;
        const uint8_t* sBlo = sb + B_LO_OFF;

        uint32_t af[2][4][4];
        #pragma unroll
        for (int fm = 0; fm < 4; ++fm)
            #pragma unroll
            for (int q = 0; q < 4; ++q) {
                af[0][fm][q] = *(const uint32_t*)(sAhi + offA[fm][q]);
                af[1][fm][q] = *(const uint32_t*)(sAlo + offA[fm][q]);
            }
        #pragma unroll
        for (int fn = 0; fn < 8; ++fn) {
            uint32_t bh0 = *(const uint32_t*)(sBhi + offB[fn][0]);
            uint32_t bh1 = *(const uint32_t*)(sBhi + offB[fn][1]);
            uint32_t bl0 = *(const uint32_t*)(sBlo + offB[fn][0]);
            uint32_t bl1 = *(const uint32_t*)(sBlo + offB[fn][1]);
            #pragma unroll
            for (int fm = 0; fm < 4; ++fm) {
                mma_bf16(acc[fm][fn], af[0][fm], bh0, bh1);   // hi*hi
                mma_bf16(acc[fm][fn], af[0][fm], bl0, bl1);   // hi*lo
                mma_bf16(acc[fm][fn], af[1][fm], bh0, bh1);   // lo*hi
            }
        }

        // stage (c+1) complete (cp.async + STS) before anyone reads it
        cpa_wait<0>();
        __syncthreads();
    }

    // ---- epilogue ----------------------------------------------------------
    float* Cout = (MODE == 0) ? g_t : outC;
    #pragma unroll
    for (int fm = 0; fm < 4; ++fm) {
        size_t r0 = rowBase + wm * 64 + fm * 16 + g;
        size_t r1 = r0 + 8;
        #pragma unroll
        for (int fn = 0; fn < 8; ++fn) {
            int col = n0 + wn * 64 + fn * 8 + 2 * tig;
            float2 v0, v1;
            if (MODE == 0) {
                v0.x = acc[fm][fn][0]; v0.y = acc[fm][fn][1];
                v1.x = acc[fm][fn][2]; v1.y = acc[fm][fn][3];
            } else {
                float bx = bias[col], by = bias[col + 1];
                v0.x = tanhf(acc[fm][fn][0] + bx);
                v0.y = tanhf(acc[fm][fn][1] + by);
                v1.x = tanhf(acc[fm][fn][2] + bx);
                v1.y = tanhf(acc[fm][fn][3] + by);
            }
            *(float2*)(Cout + r0 * HH + col) = v0;
            *(float2*)(Cout + r1 * HH + col) = v1;
        }
    }
}

// ---------------- per-graph aggregation (CSR, register accumulation) --------
template<int L>
__global__ void __launch_bounds__(64) agg_k(const float* __restrict__ bias)
{
    __shared__ float    sIn [TT * CH];
    __shared__ float    sNrm[EPG];
    __shared__ uint16_t sSrc[EPG];
    __shared__ int      sRp [TT + 1];
    __shared__ float    sSelf[TT];

    float* pout = (L == 0) ? g_p1 : (L == 1) ? g_p2 : g_p3;

    const int b   = blockIdx.x;
    const int c0  = blockIdx.y * CH;
    const int c   = threadIdx.x;

    const float* base = g_t + (size_t)b * TT * HH + c0;
    for (int i = c; i < TT * CH; i += 64) {
        int node = i / CH, ch = i & (CH - 1);
        sIn[i] = base[(size_t)node * HH + ch];
    }
    for (int e = c; e < EPG; e += 64) {
        sNrm[e] = g_srt_nrm[b * EPG + e];
        sSrc[e] = g_srt_src[b * EPG + e];
    }
    for (int i = c; i <= TT; i += 64) sRp[i] = g_rp[b][i];
    for (int i = c; i < TT; i += 64) {
        float d = g_dinv[b * TT + i];
        sSelf[i] = d * d;
    }
    __syncthreads();

    const float bc = bias[c0 + c];
    float sum = 0.f, sq = 0.f;
    for (int node = 0; node < TT; ++node) {
        float acc = 0.f;
        const int e1 = sRp[node + 1];
        for (int e = sRp[node]; e < e1; ++e)
            acc = fmaf(sIn[sSrc[e] * CH + c], sNrm[e], acc);
        float v = acc + sIn[node * CH + c] * sSelf[node] + bc;
        pout[(size_t)(b * TT + node) * HH + c0 + c] = v;
        sum += v;
        sq  += v * v;
    }
    atomicAdd(&g_stats[c0 + c], sum);
    atomicAdd(&g_stats[HH + c0 + c], sq);
}

// ---------------- BN finalize ------------------------------------------------
template<int L>
__global__ void bnfinal_k(const float* __restrict__ g, const float* __restrict__ be)
{
    int c = threadIdx.x;
    float s = g_stats[c], sq = g_stats[HH + c];
    const float inv = 1.0f / (float)NN;
    float mean = s * inv;
    float var  = sq * inv - mean * mean;
    float rstd = rsqrtf(var + 1e-5f);
    float scl  = g[c] * rstd;
    g_scale[L * HH + c] = scl;
    g_shift[L * HH + c] = fmaf(-mean, scl, be[c]);
    g_stats[c] = 0.f;
    g_stats[HH + c] = 0.f;
}

// ---------------- host driver: kernel launches ONLY --------------------------
extern "C" void kernel_launch(void* const* d_in, const int* in_sizes, int n_in,
                              void* d_out, int out_size)
{
    (void)in_sizes; (void)n_in; (void)out_size;

    const float* x      = (const float*)d_in[0];
    const int*   eidx   = (const int*)  d_in[1];
    const int*   esrc   = eidx;
    const int*   edst   = eidx + EE;
    const float* ew     = (const float*)d_in[2];
    const int*   pos    = (const int*)  d_in[3];
    const float* posemb = (const float*)d_in[4];
    const float* W1 = (const float*)d_in[5];
    const float* b1 = (const float*)d_in[6];
    const float* g1 = (const float*)d_in[7];
    const float* be1= (const float*)d_in[8];
    const float* W2 = (const float*)d_in[9];
    const float* b2 = (const float*)d_in[10];
    const float* g2 = (const float*)d_in[11];
    const float* be2= (const float*)d_in[12];
    const float* W3 = (const float*)d_in[13];
    const float* b3 = (const float*)d_in[14];
    const float* g3 = (const float*)d_in[15];
    const float* be3= (const float*)d_in[16];
    const float* Wl = (const float*)d_in[17];
    const float* bl = (const float*)d_in[18];
    float* out = (float*)d_out;

    dim3 aGrid(NB, HH / CH);          // (2048, 8)
    dim3 gGrid(HH / 256, NN / 128);   // (2, 800)
    dim3 wGrid1(KIN / 64, HH / 64);   // (9, 8)
    dim3 wGridH(HH / 64, HH / 64);    // (8, 8)

    // ordered so gemm1 is launch index 3 (profiled slot)
    wprep_k<0><<<wGrid1, 256>>>(W1);                      // 0
    deg_init_k<<<(NN + 255) / 256, 256>>>();              // 1
    deg_acc_k<<<(EE + 255) / 256, 256>>>(edst, ew);       // 2
    gemm_hmma<0, 0, -1, KIN, 0><<<gGrid, 256>>>(x, pos, posemb, nullptr, nullptr); // 3
    dinv_k<<<(NN + 255) / 256, 256>>>();                  // 4
    norm_k<<<(EE + 255) / 256, 256>>>(esrc, edst, ew);    // 5
    csr_k<<<NB, 64>>>(esrc, edst);                        // 6
    wprep_k<1><<<wGridH, 256>>>(W2);                      // 7

    // layer 1 aggregation + BN
    agg_k<0><<<aGrid, 64>>>(b1);
    bnfinal_k<0><<<1, HH>>>(g1, be1);

    // layer 2 (A = p1 with fused BN0+ReLU+split)
    gemm_hmma<0, 1, 0, HH, 1><<<gGrid, 256>>>(nullptr, nullptr, nullptr, nullptr, nullptr);
    wprep_k<2><<<wGridH, 256>>>(W3);
    agg_k<1><<<aGrid, 64>>>(b2);
    bnfinal_k<1><<<1, HH>>>(g2, be2);

    // layer 3 (A = p2 with fused BN1+ReLU+split)
    gemm_hmma<0, 2, 1, HH, 2><<<gGrid, 256>>>(nullptr, nullptr, nullptr, nullptr, nullptr);
    wprep_k<3><<<wGridH, 256>>>(Wl);
    agg_k<2><<<aGrid, 64>>>(b3);
    bnfinal_k<2><<<1, HH>>>(g3, be3);

    // residual combine (fp32) + final head (A = g_t, split on the fly)
    combine_k<<<(NN * HH / 4) / 256, 256>>>();
    gemm_hmma<1, 3, -1, HH, 3><<<gGrid, 256>>>(nullptr, nullptr, nullptr, out, bl);
}